// round 2
// baseline (speedup 1.0000x reference)
#include <cuda_runtime.h>
#include <cstdint>

// GroupQuantizedLinear: y = (round(clip(W,-8,7)) * scale_per_group) @ x
// W: [8192, 8192] f32, scales: [8192, 64] f32 (group size 128), x: [8192] f32
// Pure HBM-bound GEMV over 256 MB of weights.

static constexpr int IN_DIM  = 8192;
static constexpr int OUT_DIM = 8192;
static constexpr int GROUPS  = 64;      // group size = 128 channels
static constexpr int THREADS = 256;
static constexpr int ROWS    = 4;       // output rows per block
static constexpr int VEC4    = IN_DIM / 4;          // 2048 float4 per row
static constexpr int ITERS   = VEC4 / THREADS;      // 8 float4 loads per thread per row

__global__ __launch_bounds__(THREADS, 4)
void gql_kernel(const float* __restrict__ x,
                const float* __restrict__ w,
                const float* __restrict__ scales,
                float* __restrict__ out)
{
    __shared__ float4 xs[VEC4];          // 32 KB: x staged once per block
    __shared__ float  red[THREADS / 32]; // per-warp partials

    const int t = threadIdx.x;

    // Stage x into shared (coalesced float4)
    const float4* x4 = reinterpret_cast<const float4*>(x);
    #pragma unroll
    for (int i = t; i < VEC4; i += THREADS) xs[i] = x4[i];
    __syncthreads();

    const int row0 = blockIdx.x * ROWS;

    #pragma unroll
    for (int r = 0; r < ROWS; r++) {
        const int o = row0 + r;
        const float4* w4   = reinterpret_cast<const float4*>(w + (size_t)o * IN_DIM);
        const float*  srow = scales + o * GROUPS;

        float acc = 0.0f;
        #pragma unroll
        for (int it = 0; it < ITERS; it++) {
            const int i4 = t + it * THREADS;      // float4 index within row
            const float4 wv = __ldcs(w4 + i4);    // streaming (evict-first) weight read
            const float  sc = __ldg(srow + (i4 >> 5));  // group = (4*i4)/128
            const float4 xv = xs[i4];

            // fake-quant: clip to [-8,7], round-half-to-even (matches jnp.round)
            const float q0 = rintf(fminf(fmaxf(wv.x, -8.0f), 7.0f));
            const float q1 = rintf(fminf(fmaxf(wv.y, -8.0f), 7.0f));
            const float q2 = rintf(fminf(fmaxf(wv.z, -8.0f), 7.0f));
            const float q3 = rintf(fminf(fmaxf(wv.w, -8.0f), 7.0f));

            acc += sc * (q0 * xv.x + q1 * xv.y + q2 * xv.z + q3 * xv.w);
        }

        // warp reduce
        #pragma unroll
        for (int off = 16; off; off >>= 1)
            acc += __shfl_xor_sync(0xFFFFFFFFu, acc, off);
        if ((t & 31) == 0) red[t >> 5] = acc;
        __syncthreads();

        if (t < THREADS / 32) {
            float v = red[t];
            #pragma unroll
            for (int off = (THREADS / 64); off; off >>= 1)
                v += __shfl_xor_sync((1u << (THREADS / 32)) - 1u, v, off);
            if (t == 0) out[o] = v;
        }
        __syncthreads();
    }
}

extern "C" void kernel_launch(void* const* d_in, const int* in_sizes, int n_in,
                              void* d_out, int out_size)
{
    const float* x      = (const float*)d_in[0];   // [8192]
    const float* w      = (const float*)d_in[1];   // [8192*8192]
    const float* scales = (const float*)d_in[2];   // [8192*64]
    float* out = (float*)d_out;                    // [8192]

    gql_kernel<<<OUT_DIM / ROWS, THREADS>>>(x, w, scales, out);
}

// round 4
// speedup vs baseline: 1.0625x; 1.0625x over previous
#include <cuda_runtime.h>
#include <cstdint>

// GroupQuantizedLinear: y = (round(clip(W,-8,7)) * scale_per_group) @ x
// W: [8192, 8192] f32, scales: [8192, 64] f32 (group size 128), x: [8192] f32
// HBM-bound GEMV over 256 MB of weights. 4 rows interleaved in one streaming
// pass to maximize in-flight DRAM loads and avoid per-row pipeline drains.

static constexpr int IN_DIM  = 8192;
static constexpr int OUT_DIM = 8192;
static constexpr int GROUPS  = 64;      // group size = 128 channels = 32 float4
static constexpr int THREADS = 256;
static constexpr int ROWS    = 4;       // output rows per block, interleaved
static constexpr int VEC4    = IN_DIM / 4;          // 2048 float4 per row
static constexpr int ITERS   = VEC4 / THREADS;      // 8 float4 loads/thread/row
static constexpr int NWARP   = THREADS / 32;        // 8

__device__ __forceinline__ float qdot(float4 wv, float4 xv) {
    const float q0 = rintf(fminf(fmaxf(wv.x, -8.0f), 7.0f));
    const float q1 = rintf(fminf(fmaxf(wv.y, -8.0f), 7.0f));
    const float q2 = rintf(fminf(fmaxf(wv.z, -8.0f), 7.0f));
    const float q3 = rintf(fminf(fmaxf(wv.w, -8.0f), 7.0f));
    return q0 * xv.x + q1 * xv.y + q2 * xv.z + q3 * xv.w;
}

__global__ __launch_bounds__(THREADS, 4)
void gql_kernel(const float* __restrict__ x,
                const float* __restrict__ w,
                const float* __restrict__ scales,
                float* __restrict__ out)
{
    __shared__ float4 xs[VEC4];               // 32 KB: x staged once per block
    __shared__ float  ss[ROWS][GROUPS];       // 1 KB: scales for this block's rows
    __shared__ float  red[ROWS][NWARP];       // per-warp partials

    const int t    = threadIdx.x;
    const int row0 = blockIdx.x * ROWS;

    // Stage x (coalesced float4) and the 4 rows' scales
    const float4* x4 = reinterpret_cast<const float4*>(x);
    #pragma unroll
    for (int i = t; i < VEC4; i += THREADS) xs[i] = x4[i];
    if (t < ROWS * GROUPS) {
        const int r = t >> 6, g = t & 63;     // GROUPS = 64
        ss[r][g] = scales[(size_t)(row0 + r) * GROUPS + g];
    }
    __syncthreads();

    const float4* w0 = reinterpret_cast<const float4*>(w + (size_t)(row0 + 0) * IN_DIM);
    const float4* w1 = reinterpret_cast<const float4*>(w + (size_t)(row0 + 1) * IN_DIM);
    const float4* w2 = reinterpret_cast<const float4*>(w + (size_t)(row0 + 2) * IN_DIM);
    const float4* w3 = reinterpret_cast<const float4*>(w + (size_t)(row0 + 3) * IN_DIM);

    float acc0 = 0.0f, acc1 = 0.0f, acc2 = 0.0f, acc3 = 0.0f;

    #pragma unroll
    for (int it = 0; it < ITERS; it++) {
        const int i4 = t + it * THREADS;      // float4 index within row
        // 4 independent streaming loads — high MLP, one xv reuse
        const float4 wv0 = __ldcs(w0 + i4);
        const float4 wv1 = __ldcs(w1 + i4);
        const float4 wv2 = __ldcs(w2 + i4);
        const float4 wv3 = __ldcs(w3 + i4);
        const float4 xv  = xs[i4];
        const int    g   = i4 >> 5;           // group = (4*i4)/128

        acc0 += ss[0][g] * qdot(wv0, xv);
        acc1 += ss[1][g] * qdot(wv1, xv);
        acc2 += ss[2][g] * qdot(wv2, xv);
        acc3 += ss[3][g] * qdot(wv3, xv);
    }

    // Warp-level reduction of all 4 accumulators
    #pragma unroll
    for (int off = 16; off; off >>= 1) {
        acc0 += __shfl_xor_sync(0xFFFFFFFFu, acc0, off);
        acc1 += __shfl_xor_sync(0xFFFFFFFFu, acc1, off);
        acc2 += __shfl_xor_sync(0xFFFFFFFFu, acc2, off);
        acc3 += __shfl_xor_sync(0xFFFFFFFFu, acc3, off);
    }
    const int wid = t >> 5, lane = t & 31;
    if (lane == 0) {
        red[0][wid] = acc0;
        red[1][wid] = acc1;
        red[2][wid] = acc2;
        red[3][wid] = acc3;
    }
    __syncthreads();

    // Warps 0..3 each reduce one row's NWARP partials; all 32 lanes participate.
    if (wid < ROWS) {
        float v = (lane < NWARP) ? red[wid][lane] : 0.0f;
        #pragma unroll
        for (int off = NWARP / 2; off; off >>= 1)
            v += __shfl_xor_sync(0xFFFFFFFFu, v, off);
        if (lane == 0) out[row0 + wid] = v;
    }
}

extern "C" void kernel_launch(void* const* d_in, const int* in_sizes, int n_in,
                              void* d_out, int out_size)
{
    const float* x      = (const float*)d_in[0];   // [8192]
    const float* w      = (const float*)d_in[1];   // [8192*8192]
    const float* scales = (const float*)d_in[2];   // [8192*64]
    float* out = (float*)d_out;                    // [8192]

    gql_kernel<<<OUT_DIM / ROWS, THREADS>>>(x, w, scales, out);
}